// round 17
// baseline (speedup 1.0000x reference)
#include <cuda_runtime.h>
#include <cuda_fp16.h>
#include <math.h>
#include <stdint.h>

// ---------------- problem constants ----------------
#define L_   12
#define B_   4
#define S_   512
#define D_   768
#define H_   12
#define DH_  64
#define FF_  3072
#define BH_  (B_*H_)        // 48
#define MR_  (B_*S_)        // 2048
#define SS_  (S_*S_)        // 262144

// ---------------- scratch (device globals; allocation-free) ----------------
__device__ __half g_bias16[BH_*SS_];   // fp16 attention bias (layer-invariant)
__device__ __half g_q16 [BH_*S_*DH_];  // fp16 (flash input)
__device__ __half g_k16 [BH_*S_*DH_];
__device__ __half g_v16 [BH_*S_*DH_];
__device__ __half g_ctx16[MR_*D_];     // flash output (fp16)
__device__ float  g_h   [MR_*D_];      // fp32 residual
__device__ __half g_h16 [MR_*D_];      // fp16 shadow
__device__ float  g_attn[MR_*D_];      // fp32 residual
__device__ __half g_attn16[MR_*D_];    // fp16 shadow
__device__ __half g_ff16[MR_*FF_];     // gelu out (fp16)
__device__ float  g_part[2*MR_*D_];    // split-K partials (fp32)
// pre-transposed fp16 weights [N][K]
__device__ __half g_wq16 [L_*D_*D_];
__device__ __half g_wk16 [L_*D_*D_];
__device__ __half g_wv16 [L_*D_*D_];
__device__ __half g_wo16 [L_*D_*D_];
__device__ __half g_wi16 [L_*D_*FF_];
__device__ __half g_wo216[L_*FF_*D_];

// ---------------- helpers ----------------
__device__ __forceinline__ void mma_f16(float* c, const uint32_t* a, const uint32_t* b)
{
    asm("mma.sync.aligned.m16n8k16.row.col.f32.f16.f16.f32 "
        "{%0,%1,%2,%3}, {%4,%5,%6,%7}, {%8,%9}, {%0,%1,%2,%3};"
        : "+f"(c[0]), "+f"(c[1]), "+f"(c[2]), "+f"(c[3])
        : "r"(a[0]), "r"(a[1]), "r"(a[2]), "r"(a[3]),
          "r"(b[0]), "r"(b[1]));
}

__device__ __forceinline__ void ldsm4(uint32_t* d, uint32_t addr)
{
    asm volatile("ldmatrix.sync.aligned.m8n8.x4.shared.b16 {%0,%1,%2,%3}, [%4];"
                 : "=r"(d[0]), "=r"(d[1]), "=r"(d[2]), "=r"(d[3]) : "r"(addr));
}

__device__ __forceinline__ void ldsm4t(uint32_t& d0, uint32_t& d1,
                                       uint32_t& d2, uint32_t& d3, uint32_t addr)
{
    asm volatile("ldmatrix.sync.aligned.m8n8.x4.trans.shared.b16 "
                 "{%0,%1,%2,%3}, [%4];"
                 : "=r"(d0), "=r"(d1), "=r"(d2), "=r"(d3) : "r"(addr));
}

__device__ __forceinline__ void cp16(void* dst, const void* src)
{
    uint32_t d = (uint32_t)__cvta_generic_to_shared(dst);
    asm volatile("cp.async.cg.shared.global [%0], [%1], 16;" :: "r"(d), "l"(src));
}
#define CP_COMMIT() asm volatile("cp.async.commit_group;")

// ---------------- small kernels ----------------
__global__ void bias_kernel(const float* __restrict__ rel,
                            const float* __restrict__ rel2,
                            const float* __restrict__ mask)
{
    long i = ((long)blockIdx.x * 256 + threadIdx.x) * 2;
    if (i >= (long)BH_ * SS_) return;
    int b = (int)(i / ((long)H_ * SS_));
    int kcol = (int)(i & (S_ - 1));
    float2 r1 = *(const float2*)&rel[i];
    float2 r2 = *(const float2*)&rel2[i];
    float2 mm = *(const float2*)&mask[b * S_ + kcol];
    *(half2*)&g_bias16[i] = __floats2half2_rn(
        (r1.x + r2.x) * 0.125f + mm.x, (r1.y + r2.y) * 0.125f + mm.y);
}

// batched transpose + fp16 cvt for the four DxD weights
__global__ void transpose_cvt4_kernel(const float* __restrict__ s0, __half* d0,
                                      const float* __restrict__ s1, __half* d1,
                                      const float* __restrict__ s2, __half* d2,
                                      const float* __restrict__ s3, __half* d3)
{
    __shared__ float tile[32][33];
    const int which = blockIdx.z / L_, layer = blockIdx.z % L_;
    const float* src = which == 0 ? s0 : which == 1 ? s1 : which == 2 ? s2 : s3;
    __half* dst = which == 0 ? d0 : which == 1 ? d1 : which == 2 ? d2 : d3;
    const long lz = (long)layer * D_ * D_;
    const int k0 = blockIdx.y * 32, n0 = blockIdx.x * 32;
    const int tx = threadIdx.x, ty = threadIdx.y;   // 32 x 8
#pragma unroll
    for (int i = 0; i < 32; i += 8)
        tile[ty + i][tx] = src[lz + (long)(k0 + ty + i) * D_ + n0 + tx];
    __syncthreads();
#pragma unroll
    for (int i = 0; i < 32; i += 8)
        dst[lz + (long)(n0 + ty + i) * D_ + k0 + tx] = __float2half(tile[tx][ty + i]);
}

__global__ void transpose_cvt_kernel(const float* __restrict__ src,
                                     __half* __restrict__ dst, int K, int N)
{
    __shared__ float tile[32][33];
    const long lz = (long)blockIdx.z * K * N;
    const int k0 = blockIdx.y * 32, n0 = blockIdx.x * 32;
    const int tx = threadIdx.x, ty = threadIdx.y;
#pragma unroll
    for (int i = 0; i < 32; i += 8)
        tile[ty + i][tx] = src[lz + (long)(k0 + ty + i) * N + n0 + tx];
    __syncthreads();
#pragma unroll
    for (int i = 0; i < 32; i += 8)
        dst[lz + (long)(n0 + ty + i) * K + k0 + tx] = __float2half(tile[tx][ty + i]);
}

__global__ void copy2_kernel(const float* __restrict__ src, float* __restrict__ dst,
                             __half* __restrict__ dst16, long n)
{
    long i = (long)blockIdx.x * 256 + threadIdx.x;
    if (i < n) { float v = src[i]; dst[i] = v; dst16[i] = __float2half(v); }
}

// ---------------- fused flash attention (v5: ldmatrix everywhere) -----------
// word offsets: K[2] @0 (2304 ea), V[2] @4608, Q/P @9216, bias[2] @11520
#define FLASH_SMEM (16128 * 4)   // 64512 B -> 3 CTAs/SM

__global__ __launch_bounds__(128, 3)
void flash_attn(const __half* __restrict__ Qg, const __half* __restrict__ Kg,
                const __half* __restrict__ Vg, const __half* __restrict__ biasg,
                __half* __restrict__ ctx)
{
    extern __shared__ uint32_t smw[];

    const int z  = blockIdx.y;
    const int q0 = blockIdx.x * 64;
    const int tid  = threadIdx.x;
    const int warp = tid >> 5, lane = tid & 31;
    const int g = lane >> 2, tig = lane & 3;

    const __half* Qz = Qg + (long)z * S_ * DH_;
    const __half* Kz = Kg + (long)z * S_ * DH_;
    const __half* Vz = Vg + (long)z * S_ * DH_;
    const __half* bz = biasg + (long)z * SS_;

    auto loadKVB = [&](int s, int kt) {
        __half* Kh = (__half*)(smw + s * 2304);
        __half* Vh = (__half*)(smw + 4608 + s * 2304);
        __half* Bh = (__half*)(smw + 11520 + s * 2304);
#pragma unroll
        for (int i = 0; i < 4; i++) {
            int idx = i * 128 + tid;
            int n = idx >> 3, c8 = (idx & 7) << 3;
            cp16(Kh + n * 72 + c8, Kz + (long)(kt * 64 + n) * DH_ + c8);
            cp16(Vh + n * 72 + c8, Vz + (long)(kt * 64 + n) * DH_ + c8);
            cp16(Bh + n * 72 + c8, bz + (long)(q0 + n) * S_ + kt * 64 + c8);
        }
    };

    {
        __half* Qh = (__half*)(smw + 9216);
#pragma unroll
        for (int i = 0; i < 4; i++) {
            int idx = i * 128 + tid;
            int m = idx >> 3, c8 = (idx & 7) << 3;
            cp16(Qh + m * 72 + c8, Qz + (long)(q0 + m) * DH_ + c8);
        }
    }
    loadKVB(0, 0);
    CP_COMMIT();
    asm volatile("cp.async.wait_group 0;");
    __syncthreads();

    const int r = warp * 16 + g;
    const uint32_t smem_u = (uint32_t)__cvta_generic_to_shared(smw);

    const int a_r = warp * 16 + (lane & 7) + ((lane >> 3) & 1) * 8;
    const int a_w = (lane >> 4) << 2;
    const int b_r = (lane & 7) + ((lane >> 4) << 3);
    const int b_w = ((lane >> 3) & 1) << 2;

    uint32_t afq[4][4];
#pragma unroll
    for (int ks = 0; ks < 4; ks++)
        ldsm4(afq[ks], smem_u + (9216 + a_r * 36 + ks * 8 + a_w) * 4);
    __syncthreads();

    float acc[8][4] = {};
    float mrow0 = -1e30f, mrow1 = -1e30f;
    float l0 = 0.0f, l1 = 0.0f;
    int buf = 0;

    uint32_t* P2 = smw + 9216;
    const int lm = lane & 15, hi8 = (lane >> 4) << 3;

    for (int kt = 0; kt < 8; kt++) {
        if (kt < 7) loadKVB(buf ^ 1, kt + 1);
        CP_COMMIT();

        const uint32_t koff = smem_u + (buf * 2304) * 4;
        float s[8][4] = {};
#pragma unroll
        for (int ks = 0; ks < 4; ks++) {
            uint32_t bf[8][2];
#pragma unroll
            for (int p = 0; p < 4; p++) {
                uint32_t d[4];
                ldsm4(d, koff + ((b_r + p * 16) * 36 + ks * 8 + b_w) * 4);
                bf[2 * p][0] = d[0]; bf[2 * p][1] = d[1];
                bf[2 * p + 1][0] = d[2]; bf[2 * p + 1][1] = d[3];
            }
#pragma unroll
            for (int nt = 0; nt < 8; nt++)
                mma_f16(s[nt], afq[ks], bf[nt]);
        }

        const __half* bp = (const __half*)(smw + 11520 + buf * 2304);
        float nm0 = mrow0, nm1 = mrow1;
#pragma unroll
        for (int nt = 0; nt < 8; nt++) {
            int c = nt * 8 + 2 * tig;
            float2 b0 = __half22float2(*(const half2*)(bp + r * 72 + c));
            float2 b1 = __half22float2(*(const half2*)(bp + (r + 8) * 72 + c));
            s[nt][0] += b0.x; s[nt][1] += b0.y;
            s[nt][2] += b1.x; s[nt][3] += b1.y;
            nm0 = fmaxf(nm0, fmaxf(s[nt][0], s[nt][1]));
            nm1 = fmaxf(nm1, fmaxf(s[nt][2], s[nt][3]));
        }
        nm0 = fmaxf(nm0, __shfl_xor_sync(0xffffffffu, nm0, 1));
        nm0 = fmaxf(nm0, __shfl_xor_sync(0xffffffffu, nm0, 2));
        nm1 = fmaxf(nm1, __shfl_xor_sync(0xffffffffu, nm1, 1));
        nm1 = fmaxf(nm1, __shfl_xor_sync(0xffffffffu, nm1, 2));

        float alpha0 = __expf(mrow0 - nm0);
        float alpha1 = __expf(mrow1 - nm1);
        mrow0 = nm0; mrow1 = nm1;

        float rs0 = 0.0f, rs1 = 0.0f;
#pragma unroll
        for (int nt = 0; nt < 8; nt++) {
            float p0 = __expf(s[nt][0] - nm0);
            float p1 = __expf(s[nt][1] - nm0);
            float p2 = __expf(s[nt][2] - nm1);
            float p3 = __expf(s[nt][3] - nm1);
            rs0 += p0 + p1; rs1 += p2 + p3;
            half2 h01 = __floats2half2_rn(p0, p1);
            half2 h23 = __floats2half2_rn(p2, p3);
            P2[r * 36 + nt * 4 + tig]       = *(uint32_t*)&h01;
            P2[(r + 8) * 36 + nt * 4 + tig] = *(uint32_t*)&h23;
            acc[nt][0] *= alpha0; acc[nt][1] *= alpha0;
            acc[nt][2] *= alpha1; acc[nt][3] *= alpha1;
        }
        rs0 += __shfl_xor_sync(0xffffffffu, rs0, 1);
        rs0 += __shfl_xor_sync(0xffffffffu, rs0, 2);
        rs1 += __shfl_xor_sync(0xffffffffu, rs1, 1);
        rs1 += __shfl_xor_sync(0xffffffffu, rs1, 2);
        l0 = l0 * alpha0 + rs0;
        l1 = l1 * alpha1 + rs1;
        __syncwarp();

        const uint32_t psh = smem_u + 9216 * 4;
        const uint32_t vsh = smem_u + (4608 + buf * 2304) * 4;
#pragma unroll
        for (int ks = 0; ks < 4; ks++) {
            const int kk = ks * 16;
            uint32_t af[4];
            ldsm4(af, psh + (a_r * 36 + ks * 8 + a_w) * 4);
#pragma unroll
            for (int nt2 = 0; nt2 < 4; nt2++) {
                uint32_t b0, b1, b2, b3;
                uint32_t addr = vsh +
                    (((kk + lm) * 72 + nt2 * 16 + hi8) << 1);
                ldsm4t(b0, b1, b2, b3, addr);
                uint32_t bfA[2] = {b0, b1}, bfB[2] = {b2, b3};
                mma_f16(acc[nt2 * 2],     af, bfA);
                mma_f16(acc[nt2 * 2 + 1], af, bfB);
            }
        }

        if (kt < 7) {
            asm volatile("cp.async.wait_group 0;");
            __syncthreads();
        }
        buf ^= 1;
    }

    const float inv0 = 1.0f / l0, inv1 = 1.0f / l1;
    const int b = z / H_, hh = z % H_;
    const int mg = q0 + r;
    __half* out0 = ctx + (long)(b * S_ + mg) * D_ + hh * DH_;
    __half* out1 = out0 + 8 * D_;
#pragma unroll
    for (int nt = 0; nt < 8; nt++) {
        int c = nt * 8 + 2 * tig;
        *(half2*)(out0 + c) = __floats2half2_rn(acc[nt][0] * inv0, acc[nt][1] * inv0);
        *(half2*)(out1 + c) = __floats2half2_rn(acc[nt][2] * inv1, acc[nt][3] * inv1);
    }
}

// ---------------- tensor-core FP16 GEMM (3-stage, 3 CTAs/SM) ----------------
// 4 warps (2x2), warp tile 64x(BN/2). cp.async 3-stage, BK=32, ldmatrix.x4,
// fp32 accum. B frags consumed pairwise right after load (min live regs).
// EPI: 0 = raw fp32 partial store to C + z*M*N
//      1 = fused QKV scatter, fp16 out; picks {Wq,Wk,Wv} by n-block
//      3 = fp16 gelu(acc + bias[n]) to (half*)C
template<int BN, int EPI>
__global__ __launch_bounds__(128, 3)
void gemm_h(const __half* __restrict__ A, const __half* __restrict__ Bt,
            float* __restrict__ C, const float* __restrict__ bias,
            const __half* __restrict__ Bt2, const float* __restrict__ bias2,
            float* __restrict__ C2,
            const __half* __restrict__ Bt3, const float* __restrict__ bias3,
            float* __restrict__ C3,
            int M, int N, int K, int lda, int ldb, float scaleval)
{
    constexpr int BM = 128, BK = 32, STAGES = 3;
    constexpr int WM = 64, WN = BN / 2;
    constexpr int MT = WM / 16, NTL = WN / 8;   // 4, 8|4
    constexpr int STR2 = BK / 2 + 4;            // 20 half2 words
    constexpr int ASZ = BM * STR2;
    constexpr int BSZ = BN * STR2;

    extern __shared__ uint32_t sm2[];
    uint32_t* AsB = sm2;
    uint32_t* BsB = sm2 + STAGES * ASZ;

    const int zz = blockIdx.z;
    A  += (long)zz * K;
    Bt += (long)zz * K;

    int n0;
    if constexpr (EPI == 1) {
        const int nb = N / BN;
        const int which = blockIdx.x / nb;
        n0 = (blockIdx.x % nb) * BN;
        if (which == 1) { Bt = Bt2; bias = bias2; C = C2; scaleval = 1.0f; }
        else if (which == 2) { Bt = Bt3; bias = bias3; C = C3; scaleval = 1.0f; }
    } else {
        n0 = blockIdx.x * BN;
    }
    float* Cw = C;
    if constexpr (EPI == 0) Cw = C + (long)zz * M * N;

    const int m0 = blockIdx.y * BM;
    const int tid  = threadIdx.x;
    const int warp = tid >> 5, lane = tid & 31;
    const int g = lane >> 2, tig = lane & 3;
    const int wm = warp & 1, wn = warp >> 1;
    const int m_base = wm * WM, n_base = wn * WN;

    const uint32_t smem_u = (uint32_t)__cvta_generic_to_shared(sm2);
    const int a_r = m_base + (lane & 7) + ((lane >> 3) & 1) * 8;
    const int a_w = (lane >> 4) << 2;
    const int b_r = n_base + (lane & 7) + ((lane >> 4) << 3);
    const int b_w = ((lane >> 3) & 1) << 2;

    float acc[MT][NTL][4] = {};

    auto loadTiles = [&](int stage, int kt) {
        const int k0 = kt * BK;
        uint32_t* as = AsB + stage * ASZ;
        uint32_t* bs = BsB + stage * BSZ;
#pragma unroll
        for (int i = 0; i < 4; i++) {           // A: 128 rows x 4 chunks
            int id = i * 128 + tid;
            int m = id >> 2, j = id & 3;
            cp16(&as[m * STR2 + 4 * j], A + (long)(m0 + m) * lda + k0 + 8 * j);
        }
#pragma unroll
        for (int i = 0; i < BN / 32; i++) {     // B: BN rows x 4 chunks
            int id = i * 128 + tid;
            int n = id >> 2, j = id & 3;
            cp16(&bs[n * STR2 + 4 * j], Bt + (long)(n0 + n) * ldb + k0 + 8 * j);
        }
    };

    auto compute = [&](int stage) {
        const uint32_t aoff = smem_u + (stage * ASZ) * 4;
        const uint32_t boff = smem_u + (STAGES * ASZ + stage * BSZ) * 4;
#pragma unroll
        for (int ks = 0; ks < 2; ks++) {
            const int kk2 = ks * 8;
            uint32_t af[MT][4];
#pragma unroll
            for (int mt = 0; mt < MT; mt++)
                ldsm4(af[mt], aoff + ((a_r + mt * 16) * STR2 + kk2 + a_w) * 4);
#pragma unroll
            for (int p = 0; p < NTL / 2; p++) {
                uint32_t d[4];
                ldsm4(d, boff + ((b_r + p * 16) * STR2 + kk2 + b_w) * 4);
                uint32_t bfA[2] = {d[0], d[1]}, bfB[2] = {d[2], d[3]};
#pragma unroll
                for (int mt = 0; mt < MT; mt++) {
                    mma_f16(acc[mt][2 * p],     af[mt], bfA);
                    mma_f16(acc[mt][2 * p + 1], af[mt], bfB);
                }
            }
        }
    };

    const int KT = K / BK;
    loadTiles(0, 0); CP_COMMIT();
    loadTiles(1, 1); CP_COMMIT();

    int cur = 0, pfs = 2;
    for (int kt = 0; kt < KT; kt++) {
        asm volatile("cp.async.wait_group 1;");
        __syncthreads();
        const int pf = kt + 2;
        if (pf < KT) loadTiles(pfs, pf);
        CP_COMMIT();
        compute(cur);
        if (++cur == STAGES) cur = 0;
        if (++pfs == STAGES) pfs = 0;
    }

#pragma unroll
    for (int mt = 0; mt < MT; mt++) {
        int r0 = m0 + m_base + mt * 16 + g;
#pragma unroll
        for (int nt = 0; nt < NTL; nt++) {
            int c0 = n0 + n_base + nt * 8 + 2 * tig;
            float v0 = acc[mt][nt][0], v1 = acc[mt][nt][1];
            float v2 = acc[mt][nt][2], v3 = acc[mt][nt][3];
            if constexpr (EPI == 0) {
                *(float2*)&Cw[(long)r0 * N + c0]       = make_float2(v0, v1);
                *(float2*)&Cw[(long)(r0 + 8) * N + c0] = make_float2(v2, v3);
            } else if constexpr (EPI == 1) {
                __half* Ch = (__half*)C;
                float2 bb = *(const float2*)&bias[c0];
                half2 w01 = __floats2half2_rn((v0 + bb.x) * scaleval,
                                              (v1 + bb.y) * scaleval);
                half2 w23 = __floats2half2_rn((v2 + bb.x) * scaleval,
                                              (v3 + bb.y) * scaleval);
                int bq = r0 >> 9, s = r0 & 511, hh = c0 >> 6, d = c0 & 63;
                long o0 = ((((long)bq * H_ + hh) * S_ + s) * DH_) + d;
                *(half2*)&Ch[o0]           = w01;
                *(half2*)&Ch[o0 + 8 * DH_] = w23;
            } else if constexpr (EPI == 3) {
                __half* Ch = (__half*)C;
                float2 bb = *(const float2*)&bias[c0];
                float x0 = v0 + bb.x, x1 = v1 + bb.y;
                float x2 = v2 + bb.x, x3 = v3 + bb.y;
                float w0 = 0.5f * x0 * (1.0f + erff(x0 * 0.70710678118654752f));
                float w1 = 0.5f * x1 * (1.0f + erff(x1 * 0.70710678118654752f));
                float w2 = 0.5f * x2 * (1.0f + erff(x2 * 0.70710678118654752f));
                float w3 = 0.5f * x3 * (1.0f + erff(x3 * 0.70710678118654752f));
                *(half2*)&Ch[(long)r0 * N + c0]       = __floats2half2_rn(w0, w1);
                *(half2*)&Ch[(long)(r0 + 8) * N + c0] = __floats2half2_rn(w2, w3);
            }
        }
    }
}

// ---- layernorm 768 with fused split-K reduce: x = p0 + p1 + bias + res ----
__global__ __launch_bounds__(256)
void layernorm768_red(const float* __restrict__ part, const float* __restrict__ bvec,
                      const float* __restrict__ res, const float* __restrict__ g,
                      const float* __restrict__ b, float* __restrict__ y,
                      __half* __restrict__ y16)
{
    const long off = (long)blockIdx.x * D_;
    const float* p0 = part + off;
    const float* p1 = part + (long)MR_ * D_ + off;
    const float* rr = res + off;
    float*  orow  = y   + off;
    __half* orow2 = y16 + off;
    int tid = threadIdx.x;
    float a0 = p0[tid]       + p1[tid]       + bvec[tid]       + rr[tid];
    float a1 = p0[tid + 256] + p1[tid + 256] + bvec[tid + 256] + rr[tid + 256];
    float a2 = p0[tid + 512] + p1[tid + 512] + bvec[tid + 512] + rr[tid + 512];
    float s = a0 + a1 + a2;
    float q = a0 * a0 + a1 * a1 + a2 * a2;
    __shared__ float rs[8], rq[8];
#pragma unroll
    for (int o = 16; o; o >>= 1) {
        s += __shfl_xor_sync(0xffffffffu, s, o);
        q += __shfl_xor_sync(0xffffffffu, q, o);
    }
    if ((tid & 31) == 0) { rs[tid >> 5] = s; rq[tid >> 5] = q; }
    __syncthreads();
    s = (rs[0] + rs[1]) + (rs[2] + rs[3]) + (rs[4] + rs[5]) + (rs[6] + rs[7]);
    q = (rq[0] + rq[1]) + (rq[2] + rq[3]) + (rq[4] + rq[5]) + (rq[6] + rq[7]);
    float mean = s * (1.0f / D_);
    float var  = q * (1.0f / D_) - mean * mean;
    float r = rsqrtf(var + 1e-5f);
    float v0 = (a0 - mean) * r * g[tid]       + b[tid];
    float v1 = (a1 - mean) * r * g[tid + 256] + b[tid + 256];
    float v2 = (a2 - mean) * r * g[tid + 512] + b[tid + 512];
    orow[tid]        = v0;  orow[tid + 256]  = v1;  orow[tid + 512]  = v2;
    orow2[tid]       = __float2half(v0);
    orow2[tid + 256] = __float2half(v1);
    orow2[tid + 512] = __float2half(v2);
}

// ---------------- host orchestration ----------------
extern "C" void kernel_launch(void* const* d_in, const int* in_sizes, int n_in,
                              void* d_out, int out_size)
{
    const float* hs    = (const float*)d_in[0];
    const float* mask  = (const float*)d_in[1];
    const float* rel   = (const float*)d_in[2];
    const float* rel2  = (const float*)d_in[3];
    const float* Wq    = (const float*)d_in[4];
    const float* bq    = (const float*)d_in[5];
    const float* Wk    = (const float*)d_in[6];
    const float* bk    = (const float*)d_in[7];
    const float* Wv    = (const float*)d_in[8];
    const float* bv    = (const float*)d_in[9];
    const float* Wo    = (const float*)d_in[10];
    const float* bo    = (const float*)d_in[11];
    const float* ln1g  = (const float*)d_in[12];
    const float* ln1b  = (const float*)d_in[13];
    const float* Wi    = (const float*)d_in[14];
    const float* bi    = (const float*)d_in[15];
    const float* Wo2   = (const float*)d_in[16];
    const float* bo2   = (const float*)d_in[17];
    const float* ln2g  = (const float*)d_in[18];
    const float* ln2b  = (const float*)d_in[19];
    float* out = (float*)d_out;

    float *p_h, *p_attn, *p_part;
    __half *p_bias16, *p_q16, *p_k16, *p_v16, *p_ctx16, *p_h16, *p_attn16, *p_ff16;
    __half *p_wq, *p_wk, *p_wv, *p_wo, *p_wi, *p_wo2;
    cudaGetSymbolAddress((void**)&p_bias16, g_bias16);
    cudaGetSymbolAddress((void**)&p_q16,    g_q16);
    cudaGetSymbolAddress((void**)&p_k16,    g_k16);
    cudaGetSymbolAddress((void**)&p_v16,    g_v16);
    cudaGetSymbolAddress((void**)&p_ctx16,  g_ctx16);
    cudaGetSymbolAddress((void**)&p_h,      g_h);
    cudaGetSymbolAddress((void**)&p_h16,    g_h16);
    cudaGetSymbolAddress((void**)&p_attn,   g_attn);
    cudaGetSymbolAddress((void**)&p_attn16, g_attn16);
    cudaGetSymbolAddress((void**)&p_ff16,   g_ff16);
    cudaGetSymbolAddress((void**)&p_part,   g_part);
    cudaGetSymbolAddress((void**)&p_wq,     g_wq16);
    cudaGetSymbolAddress((void**)&p_wk,     g_wk16);
    cudaGetSymbolAddress((void**)&p_wv,     g_wv16);
    cudaGetSymbolAddress((void**)&p_wo,     g_wo16);
    cudaGetSymbolAddress((void**)&p_wi,     g_wi16);
    cudaGetSymbolAddress((void**)&p_wo2,    g_wo216);

    cudaFuncSetAttribute(flash_attn,
                         cudaFuncAttributeMaxDynamicSharedMemorySize, FLASH_SMEM);
    const int SM_BN128 = 3 * (2560 + 128 * 20) * 4;   // 61440 B -> 3 CTAs/SM
    const int SM_BN64  = 3 * (2560 + 64 * 20) * 4;    // 46080 B -> 3 CTAs/SM
    cudaFuncSetAttribute(gemm_h<128,1>,
                         cudaFuncAttributeMaxDynamicSharedMemorySize, SM_BN128);
    cudaFuncSetAttribute(gemm_h<128,3>,
                         cudaFuncAttributeMaxDynamicSharedMemorySize, SM_BN128);
    cudaFuncSetAttribute(gemm_h<64,0>,
                         cudaFuncAttributeMaxDynamicSharedMemorySize, SM_BN64);

    // ---- prep: weight transpose->fp16 (QKVO batched), bias fp16, h/h16 ----
    dim3 tb(32, 8);
    dim3 gDD4(D_ / 32, D_ / 32, 4 * L_);
    dim3 gWi(FF_ / 32, D_ / 32, L_);
    dim3 gWo2(D_ / 32, FF_ / 32, L_);
    transpose_cvt4_kernel<<<gDD4, tb>>>(Wq, p_wq, Wk, p_wk, Wv, p_wv, Wo, p_wo);
    transpose_cvt_kernel<<<gWi, tb>>>(Wi,  p_wi,  D_, FF_);
    transpose_cvt_kernel<<<gWo2, tb>>>(Wo2, p_wo2, FF_, D_);

    long nb = (long)BH_ * SS_;
    bias_kernel<<<(unsigned)((nb / 2 + 255) / 256), 256>>>(rel, rel2, mask);
    copy2_kernel<<<(MR_ * D_ + 255) / 256, 256>>>(hs, p_h, p_h16, (long)MR_ * D_);

    dim3 gQKV(3 * D_ / 128, MR_ / 128, 1);  // 288
    dim3 gFA (S_ / 64, BH_, 1);             // 384, 3 CTAs/SM -> single wave
    dim3 gWoG(D_ / 64, MR_ / 128, 2);       // 384 (split-K=2)
    dim3 gF1 (FF_ / 128, MR_ / 128, 1);     // 384
    dim3 gF2 (D_ / 64, MR_ / 128, 2);       // 384 (split-K=2)

    for (int l = 0; l < L_; l++) {
        const __half* wq  = p_wq  + (long)l * D_ * D_;
        const __half* wk  = p_wk  + (long)l * D_ * D_;
        const __half* wv  = p_wv  + (long)l * D_ * D_;
        const __half* wo  = p_wo  + (long)l * D_ * D_;
        const __half* wi  = p_wi  + (long)l * D_ * FF_;
        const __half* wo2 = p_wo2 + (long)l * FF_ * D_;

        // fused QKV projections (q folds 1/8), fp16 scatter to [B,H,S,DH]
        gemm_h<128,1><<<gQKV, 128, SM_BN128>>>(
            p_h16, wq, (float*)p_q16, bq + l * D_,
            wk, bk + l * D_, (float*)p_k16,
            wv, bv + l * D_, (float*)p_v16,
            MR_, D_, D_, D_, D_, 0.125f);

        // fused attention (full fp16) -> ctx (fp16) [B,S,D]
        flash_attn<<<gFA, 128, FLASH_SMEM>>>(p_q16, p_k16, p_v16,
                                             p_bias16, p_ctx16);

        // ctx @ Wo (split-K=2, raw partials) -> LN1 fused reduce + bias + res
        gemm_h<64,0><<<gWoG, 128, SM_BN64>>>(
            p_ctx16, wo, p_part, nullptr,
            nullptr, nullptr, nullptr, nullptr, nullptr, nullptr,
            MR_, D_, D_ / 2, D_, D_, 1.0f);
        layernorm768_red<<<MR_, 256>>>(p_part, bo + l * D_, p_h,
                                       ln1g + l * D_, ln1b + l * D_,
                                       p_attn, p_attn16);

        // ff16 = fp16(gelu(attn @ Wi + bi))
        gemm_h<128,3><<<gF1, 128, SM_BN128>>>(
            p_attn16, wi, (float*)p_ff16, bi + l * FF_,
            nullptr, nullptr, nullptr, nullptr, nullptr, nullptr,
            MR_, FF_, D_, D_, D_, 1.0f);

        // ff @ Wo2 (split-K=2, raw partials) -> LN2 fused reduce + bias + res
        gemm_h<64,0><<<gF2, 128, SM_BN64>>>(
            p_ff16, wo2, p_part, nullptr,
            nullptr, nullptr, nullptr, nullptr, nullptr, nullptr,
            MR_, D_, FF_ / 2, FF_, FF_, 1.0f);
        float* dst = (l == L_ - 1) ? out : p_h;
        layernorm768_red<<<MR_, 256>>>(p_part, bo2 + l * D_, p_attn,
                                       ln2g + l * D_, ln2b + l * D_,
                                       dst, p_h16);
    }
}